// round 4
// baseline (speedup 1.0000x reference)
#include <cuda_runtime.h>
#include <math.h>
#include <stdint.h>

#define R        2048
#define WORDS    32          // R / 64
#define KCLS     20
#define NSC      21
#define IMGW     1333.0f
#define IMGH     800.0f
#define SCORE_TH 0.5f
#define NMS_TH   0.5f
#define TOPK     100
#define NEG_INF  __int_as_float(0xFF800000)

// ---------------- global scratch ----------------
__device__ unsigned long long g_skey  [KCLS * R];        // sorted composite keys (per-class r tiebreak)
__device__ float              g_sbox  [KCLS * 4 * R];    // sorted clipped boxes SoA
__device__ unsigned int       g_sval32[KCLS * 64];       // validity bits, sorted order
__device__ int                g_wc    [KCLS];            // #64-words covering valid prefix
__device__ unsigned long long g_mask  [(size_t)KCLS * WORDS * R]; // [cls][word][row]

__device__ __forceinline__ unsigned int fkey(float f) {
    unsigned int u = __float_as_uint(f);
    return (u & 0x80000000u) ? ~u : (u | 0x80000000u);
}
__device__ __forceinline__ float fkey_inv(unsigned int k) {
    unsigned int bits = (k & 0x80000000u) ? (k ^ 0x80000000u) : ~k;
    return __uint_as_float(bits);
}

// ---------------------------------------------------------------------------
// Kernel 1: per-class bitonic sort; emit sorted keys/boxes/validity/bound.
// grid = KCLS, block = 1024
// ---------------------------------------------------------------------------
__global__ void __launch_bounds__(1024, 1)
sort_kernel(const float* __restrict__ boxes, const float* __restrict__ scores)
{
    __shared__ unsigned long long skey[R];     // 16 KB
    __shared__ unsigned char     valpre[R];    // 2 KB
    __shared__ int               smax;

    const int c = blockIdx.x;
    const int t = threadIdx.x;
    if (t == 0) smax = -1;

    for (int r = t; r < R; r += 1024) {
        bool fin = true;
        #pragma unroll
        for (int q = 0; q < 4; q++) fin &= isfinite(boxes[r * 4 + q]);
        for (int q = 0; q < NSC; q++) fin &= isfinite(scores[r * NSC + q]);
        float s = scores[r * NSC + c];
        valpre[r] = (fin && (s > SCORE_TH)) ? 1 : 0;
        skey[r] = ((unsigned long long)fkey(s) << 32) |
                  (unsigned long long)(0xFFFFFFFFu - (unsigned)r);
    }
    __syncthreads();

    // bitonic sort, descending (equal scores -> smaller r first)
    for (unsigned int kk = 2; kk <= (unsigned)R; kk <<= 1) {
        for (unsigned int j = kk >> 1; j > 0; j >>= 1) {
            #pragma unroll
            for (int e = 0; e < 2; e++) {
                unsigned int i = (unsigned)t + (unsigned)e * 1024u;
                unsigned int ixj = i ^ j;
                if (ixj > i) {
                    unsigned long long a = skey[i], b = skey[ixj];
                    bool descBlock = ((i & kk) == 0);
                    if (descBlock ? (a < b) : (a > b)) { skey[i] = b; skey[ixj] = a; }
                }
            }
            __syncthreads();
        }
    }

    // gather: sorted clipped boxes, validity ballots, keys, bound
    #pragma unroll
    for (int e = 0; e < 2; e++) {
        int i = t + e * 1024;
        unsigned long long key = skey[i];
        unsigned int rr = 0xFFFFFFFFu - (unsigned int)(key & 0xFFFFFFFFull);
        float x1 = fminf(fmaxf(boxes[rr * 4 + 0], 0.0f), IMGW);
        float y1 = fminf(fmaxf(boxes[rr * 4 + 1], 0.0f), IMGH);
        float x2 = fminf(fmaxf(boxes[rr * 4 + 2], 0.0f), IMGW);
        float y2 = fminf(fmaxf(boxes[rr * 4 + 3], 0.0f), IMGH);
        g_sbox[c * 4 * R + 0 * R + i] = x1;
        g_sbox[c * 4 * R + 1 * R + i] = y1;
        g_sbox[c * 4 * R + 2 * R + i] = x2;
        g_sbox[c * 4 * R + 3 * R + i] = y2;
        g_skey[c * R + i] = key;
        bool v = valpre[rr] != 0;
        if (v) atomicMax(&smax, i);
        unsigned int ball = __ballot_sync(0xFFFFFFFFu, v);
        if ((t & 31) == 0) g_sval32[c * 64 + (i >> 5)] = ball;
    }
    __syncthreads();
    if (t == 0) g_wc[c] = (smax < 0) ? 0 : ((smax >> 6) + 1);
}

// ---------------------------------------------------------------------------
// Kernel 2: IoU suppression bitmask, restricted to the valid prefix.
// grid = (16, KCLS), block = 1024.  CTA covers 128 rows (4 groups of 32).
// warp w = 64-column word; mask[cls][w][j] bit k <=> IoU(j, 64w+k) > 0.5
// Only rows/cols < wc*64 are computed; everything else is never read.
// ---------------------------------------------------------------------------
__global__ void __launch_bounds__(1024, 1)
iou_mask_kernel()
{
    __shared__ float sb[4 * R];    // 32 KB sorted boxes SoA
    __shared__ float sarea[R];     // 8 KB

    const int cls = blockIdx.y;
    const int wc  = g_wc[cls];
    const int cb  = wc << 6;               // column/row bound (multiple of 64)
    const int rb  = blockIdx.x * 128;
    if (rb >= cb) return;

    for (int i = threadIdx.x; i < cb; i += 1024) {
        float x1 = g_sbox[cls * 4 * R + 0 * R + i];
        float y1 = g_sbox[cls * 4 * R + 1 * R + i];
        float x2 = g_sbox[cls * 4 * R + 2 * R + i];
        float y2 = g_sbox[cls * 4 * R + 3 * R + i];
        sb[0 * R + i] = x1; sb[1 * R + i] = y1;
        sb[2 * R + i] = x2; sb[3 * R + i] = y2;
        sarea[i] = (x2 - x1) * (y2 - y1);
    }
    __syncthreads();

    const int w    = threadIdx.x >> 5;
    const int lane = threadIdx.x & 31;
    if (w >= wc) return;

    #pragma unroll
    for (int sub = 0; sub < 4; sub++) {
        const int j = rb + (sub << 5) + lane;
        if (j >= cb) continue;
        if ((w << 6) + 63 <= j) continue;    // only columns > j matter
        float x1 = sb[0 * R + j], y1 = sb[1 * R + j];
        float x2 = sb[2 * R + j], y2 = sb[3 * R + j];
        float aj = sarea[j];
        unsigned long long bits = 0ull;
        #pragma unroll 8
        for (int k = 0; k < 64; k++) {
            int cix = (w << 6) + k;          // broadcast reads
            float xx1 = fmaxf(x1, sb[0 * R + cix]);
            float yy1 = fmaxf(y1, sb[1 * R + cix]);
            float xx2 = fminf(x2, sb[2 * R + cix]);
            float yy2 = fminf(y2, sb[3 * R + cix]);
            float ww = fmaxf(xx2 - xx1, 0.0f);
            float hh = fmaxf(yy2 - yy1, 0.0f);
            float inter = ww * hh;
            float uni = aj + sarea[cix] - inter;
            float iou = inter / fmaxf(uni, 1e-9f);
            bits |= ((unsigned long long)(iou > NMS_TH)) << k;
        }
        g_mask[((size_t)cls * WORDS + w) * R + j] = bits;
    }
}

// ---------------------------------------------------------------------------
// Kernel 3: fused chunked NMS-reduce (warp = class) + parallel rank top-100.
// grid = 1, block = 640 (20 warps).
// ---------------------------------------------------------------------------
__global__ void __launch_bounds__(640, 1)
reduce_merge_kernel(const float* __restrict__ boxes, float* __restrict__ out)
{
    __shared__ unsigned short    sJ[KCLS * TOPK];      // kept sorted-indices per class
    __shared__ unsigned long long sKeys[KCLS * TOPK];  // merged keys (score | ~flat)
    __shared__ unsigned long long outk[TOPK];
    __shared__ int scnt[KCLS];
    __shared__ int stot;

    const int t    = threadIdx.x;
    const int lane = t & 31;
    const int c    = t >> 5;                // warp id = class (0..19)

    // ---------------- phase 1: chunked greedy reduce ----------------
    {
        const int wc = g_wc[c];
        const size_t cbase = (size_t)c * WORDS;
        unsigned long long valid =
            ((unsigned long long)g_sval32[c * 64 + 2 * lane + 1] << 32) |
            (unsigned long long)g_sval32[c * 64 + 2 * lane];
        unsigned long long supp = 0ull;
        int cnt = 0;

        for (int ch = 0; ch < wc; ch++) {
            // diagonal words for this chunk (issued before the pend shfl)
            unsigned long long d0 = g_mask[(cbase + ch) * R + (ch << 6) + lane];
            unsigned long long d1 = g_mask[(cbase + ch) * R + (ch << 6) + 32 + lane];
            unsigned long long pend =
                __shfl_sync(0xFFFFFFFFu, valid & ~supp, ch);
            if (pend == 0ull) continue;

            // in-register greedy over the 64-candidate chunk
            unsigned long long cur = pend, kept = 0ull;
            while (cur) {
                int b = __ffsll((unsigned long long)cur) - 1;
                kept |= 1ull << b;
                unsigned long long w0 = __shfl_sync(0xFFFFFFFFu, d0, b & 31);
                unsigned long long w1 = __shfl_sync(0xFFFFFFFFu, d1, b & 31);
                unsigned long long dw = (b < 32) ? w0 : w1;
                cur &= ~(1ull << b);
                cur &= ~dw;                   // bits <= b already decided; harmless
            }

            // batched suppression update (independent loads -> one round trip)
            unsigned long long tmp = kept;
            while (tmp) {
                int b = __ffsll((unsigned long long)tmp) - 1;
                tmp &= tmp - 1;
                if (lane < wc)
                    supp |= g_mask[(cbase + lane) * R + (ch << 6) + b];
            }

            // record kept indices (ascending) on lane 0, capped at TOPK
            if (lane == 0) {
                unsigned long long t2 = kept;
                while (t2 && cnt < TOPK) {
                    int b = __ffsll((unsigned long long)t2) - 1;
                    t2 &= t2 - 1;
                    sJ[c * TOPK + cnt] = (unsigned short)((ch << 6) + b);
                    cnt++;
                }
            }
            cnt = __shfl_sync(0xFFFFFFFFu, cnt, 0);
        }
        if (lane == 0) scnt[c] = cnt;
    }
    __syncthreads();

    // ---------------- phase 2: build merged keys ----------------
    for (int e = t; e < KCLS * TOPK; e += 640) {
        int cc = e / TOPK, p = e % TOPK;
        unsigned long long mk = 0ull;
        if (p < scnt[cc]) {
            int j = sJ[e];
            unsigned long long k = g_skey[cc * R + j];
            unsigned int rr = 0xFFFFFFFFu - (unsigned int)(k & 0xFFFFFFFFull);
            unsigned int flat = (unsigned)cc * R + rr;
            mk = (k & 0xFFFFFFFF00000000ull) |
                 (unsigned long long)(0xFFFFFFFFu - flat);
        }
        sKeys[e] = mk;
    }
    if (t == 0) {
        int s = 0;
        for (int cc = 0; cc < KCLS; cc++) s += scnt[cc];
        stot = s;
    }
    __syncthreads();

    // ---------------- phase 3: parallel rank selection ----------------
    for (int e = t; e < KCLS * TOPK; e += 640) {
        int cc = e / TOPK, p = e % TOPK;
        if (p >= scnt[cc]) continue;
        unsigned long long key = sKeys[e];
        int rank = p;
        #pragma unroll
        for (int c2 = 0; c2 < KCLS; c2++) {
            if (c2 == cc) continue;
            int lo = 0, hi = scnt[c2];
            while (lo < hi) {
                int mid = (lo + hi) >> 1;
                if (sKeys[c2 * TOPK + mid] > key) lo = mid + 1; else hi = mid;
            }
            rank += lo;
            if (rank >= TOPK) break;
        }
        if (rank < TOPK) outk[rank] = key;
    }
    __syncthreads();

    // degenerate fallback: fewer than TOPK kept -> -inf entries, lowest
    // non-kept flat index first (matches lax.top_k over the masked matrix)
    if (t == 0 && stot < TOPK) {
        int fill = stot;
        int flat = 0;
        while (fill < TOPK) {
            int cc = flat >> 11;
            int n = scnt[cc];
            bool is_kept = false;
            for (int q = 0; q < n; q++) {
                unsigned int f2 = 0xFFFFFFFFu -
                    (unsigned int)(sKeys[cc * TOPK + q] & 0xFFFFFFFFull);
                if ((int)f2 == flat) { is_kept = true; break; }
            }
            if (!is_kept) {
                outk[fill] = ((unsigned long long)fkey(NEG_INF) << 32) |
                             (unsigned long long)(0xFFFFFFFFu - (unsigned)flat);
                fill++;
            }
            flat++;
        }
    }
    __syncthreads();

    // ---------------- phase 4: write outputs ----------------
    if (t < TOPK) {
        unsigned long long key = outk[t];
        unsigned int flat = 0xFFFFFFFFu - (unsigned int)(key & 0xFFFFFFFFull);
        float sc = fkey_inv((unsigned int)(key >> 32));
        int cls = (int)(flat >> 11);      // R = 2048 = 2^11
        int rr  = (int)(flat & 2047u);
        out[t] = sc;
        out[TOPK + t * 4 + 0] = fminf(fmaxf(boxes[rr * 4 + 0], 0.0f), IMGW);
        out[TOPK + t * 4 + 1] = fminf(fmaxf(boxes[rr * 4 + 1], 0.0f), IMGH);
        out[TOPK + t * 4 + 2] = fminf(fmaxf(boxes[rr * 4 + 2], 0.0f), IMGW);
        out[TOPK + t * 4 + 3] = fminf(fmaxf(boxes[rr * 4 + 3], 0.0f), IMGH);
        out[TOPK + TOPK * 4 + t]        = (float)cls;
        out[TOPK + TOPK * 4 + TOPK + t] = (float)rr;
    }
}

extern "C" void kernel_launch(void* const* d_in, const int* in_sizes, int n_in,
                              void* d_out, int out_size)
{
    const float* boxes  = (const float*)d_in[0];   // [2048,4]
    const float* scores = (const float*)d_in[1];   // [2048,21]
    float* out = (float*)d_out;

    sort_kernel<<<KCLS, 1024>>>(boxes, scores);
    iou_mask_kernel<<<dim3(16, KCLS), 1024>>>();
    reduce_merge_kernel<<<1, 640>>>(boxes, out);
}

// round 5
// speedup vs baseline: 1.1559x; 1.1559x over previous
#include <cuda_runtime.h>
#include <math.h>
#include <stdint.h>

#define R        2048
#define WORDS    32          // R / 64
#define KCLS     20
#define NSC      21
#define IMGW     1333.0f
#define IMGH     800.0f
#define SCORE_TH 0.5f
#define NMS_TH   0.5f
#define TOPK     100
#define NEG_INF  __int_as_float(0xFF800000)

// ---------------- global scratch ----------------
__device__ unsigned long long g_skey  [KCLS * R];        // sorted composite keys (per-class r tiebreak)
__device__ float              g_sbox  [KCLS * 4 * R];    // sorted clipped boxes SoA
__device__ unsigned int       g_sval32[KCLS * 64];       // validity bits, sorted order
__device__ int                g_wc    [KCLS];            // #64-words covering valid prefix
__device__ unsigned long long g_mask  [(size_t)KCLS * WORDS * R]; // [cls][word][row]
__device__ unsigned short    g_kidx  [KCLS * TOPK];      // kept sorted-indices (first 100/class)
__device__ int                g_kcnt  [KCLS];

__device__ __forceinline__ unsigned int fkey(float f) {
    unsigned int u = __float_as_uint(f);
    return (u & 0x80000000u) ? ~u : (u | 0x80000000u);
}
__device__ __forceinline__ float fkey_inv(unsigned int k) {
    unsigned int bits = (k & 0x80000000u) ? (k ^ 0x80000000u) : ~k;
    return __uint_as_float(bits);
}

// ---------------------------------------------------------------------------
// Kernel 1: per-class bitonic sort; emit sorted keys/boxes/validity/bound.
// grid = KCLS, block = 1024
// ---------------------------------------------------------------------------
__global__ void __launch_bounds__(1024, 1)
sort_kernel(const float* __restrict__ boxes, const float* __restrict__ scores)
{
    __shared__ unsigned long long skey[R];     // 16 KB
    __shared__ unsigned char     valpre[R];    // 2 KB
    __shared__ int               smax;

    const int c = blockIdx.x;
    const int t = threadIdx.x;
    if (t == 0) smax = -1;

    for (int r = t; r < R; r += 1024) {
        bool fin = true;
        #pragma unroll
        for (int q = 0; q < 4; q++) fin &= isfinite(boxes[r * 4 + q]);
        for (int q = 0; q < NSC; q++) fin &= isfinite(scores[r * NSC + q]);
        float s = scores[r * NSC + c];
        valpre[r] = (fin && (s > SCORE_TH)) ? 1 : 0;
        skey[r] = ((unsigned long long)fkey(s) << 32) |
                  (unsigned long long)(0xFFFFFFFFu - (unsigned)r);
    }
    __syncthreads();

    // bitonic sort, descending (equal scores -> smaller r first)
    for (unsigned int kk = 2; kk <= (unsigned)R; kk <<= 1) {
        for (unsigned int j = kk >> 1; j > 0; j >>= 1) {
            #pragma unroll
            for (int e = 0; e < 2; e++) {
                unsigned int i = (unsigned)t + (unsigned)e * 1024u;
                unsigned int ixj = i ^ j;
                if (ixj > i) {
                    unsigned long long a = skey[i], b = skey[ixj];
                    bool descBlock = ((i & kk) == 0);
                    if (descBlock ? (a < b) : (a > b)) { skey[i] = b; skey[ixj] = a; }
                }
            }
            __syncthreads();
        }
    }

    // gather: sorted clipped boxes, validity ballots, keys, bound
    #pragma unroll
    for (int e = 0; e < 2; e++) {
        int i = t + e * 1024;
        unsigned long long key = skey[i];
        unsigned int rr = 0xFFFFFFFFu - (unsigned int)(key & 0xFFFFFFFFull);
        float x1 = fminf(fmaxf(boxes[rr * 4 + 0], 0.0f), IMGW);
        float y1 = fminf(fmaxf(boxes[rr * 4 + 1], 0.0f), IMGH);
        float x2 = fminf(fmaxf(boxes[rr * 4 + 2], 0.0f), IMGW);
        float y2 = fminf(fmaxf(boxes[rr * 4 + 3], 0.0f), IMGH);
        g_sbox[c * 4 * R + 0 * R + i] = x1;
        g_sbox[c * 4 * R + 1 * R + i] = y1;
        g_sbox[c * 4 * R + 2 * R + i] = x2;
        g_sbox[c * 4 * R + 3 * R + i] = y2;
        g_skey[c * R + i] = key;
        bool v = valpre[rr] != 0;
        if (v) atomicMax(&smax, i);
        unsigned int ball = __ballot_sync(0xFFFFFFFFu, v);
        if ((t & 31) == 0) g_sval32[c * 64 + (i >> 5)] = ball;
    }
    __syncthreads();
    if (t == 0) g_wc[c] = (smax < 0) ? 0 : ((smax >> 6) + 1);
}

// ---------------------------------------------------------------------------
// Kernel 2: IoU suppression bitmask, restricted to the valid prefix.
// grid = (16, KCLS), block = 1024.  CTA covers 128 rows (4 groups of 32).
// warp w = 64-column word; mask[cls][w][j] bit k <=> IoU(j, 64w+k) > 0.5
// ---------------------------------------------------------------------------
__global__ void __launch_bounds__(1024, 1)
iou_mask_kernel()
{
    __shared__ float sb[4 * R];    // 32 KB sorted boxes SoA
    __shared__ float sarea[R];     // 8 KB

    const int cls = blockIdx.y;
    const int wc  = g_wc[cls];
    const int cb  = wc << 6;               // column/row bound (multiple of 64)
    const int rb  = blockIdx.x * 128;
    if (rb >= cb) return;

    for (int i = threadIdx.x; i < cb; i += 1024) {
        float x1 = g_sbox[cls * 4 * R + 0 * R + i];
        float y1 = g_sbox[cls * 4 * R + 1 * R + i];
        float x2 = g_sbox[cls * 4 * R + 2 * R + i];
        float y2 = g_sbox[cls * 4 * R + 3 * R + i];
        sb[0 * R + i] = x1; sb[1 * R + i] = y1;
        sb[2 * R + i] = x2; sb[3 * R + i] = y2;
        sarea[i] = (x2 - x1) * (y2 - y1);
    }
    __syncthreads();

    const int w    = threadIdx.x >> 5;
    const int lane = threadIdx.x & 31;
    if (w >= wc) return;

    #pragma unroll
    for (int sub = 0; sub < 4; sub++) {
        const int j = rb + (sub << 5) + lane;
        if (j >= cb) continue;
        if ((w << 6) + 63 <= j) continue;    // only columns > j matter
        float x1 = sb[0 * R + j], y1 = sb[1 * R + j];
        float x2 = sb[2 * R + j], y2 = sb[3 * R + j];
        float aj = sarea[j];
        unsigned long long bits = 0ull;
        #pragma unroll 8
        for (int k = 0; k < 64; k++) {
            int cix = (w << 6) + k;          // broadcast reads
            float xx1 = fmaxf(x1, sb[0 * R + cix]);
            float yy1 = fmaxf(y1, sb[1 * R + cix]);
            float xx2 = fminf(x2, sb[2 * R + cix]);
            float yy2 = fminf(y2, sb[3 * R + cix]);
            float ww = fmaxf(xx2 - xx1, 0.0f);
            float hh = fmaxf(yy2 - yy1, 0.0f);
            float inter = ww * hh;
            float uni = aj + sarea[cix] - inter;
            float iou = inter / fmaxf(uni, 1e-9f);
            bits |= ((unsigned long long)(iou > NMS_TH)) << k;
        }
        g_mask[((size_t)cls * WORDS + w) * R + j] = bits;
    }
}

// ---------------------------------------------------------------------------
// Kernel 3: chunked greedy NMS reduce.  grid = KCLS, block = 32 (one warp/SM).
// lane l owns suppressed word l.  Per 64-chunk: in-register greedy over the
// diagonal words, then ONE batched mask-row OR (independent loads, MLP).
// ---------------------------------------------------------------------------
__global__ void __launch_bounds__(32, 1)
nms_reduce_kernel()
{
    const int c    = blockIdx.x;
    const int lane = threadIdx.x;
    const int wc   = g_wc[c];
    const size_t cbase = (size_t)c * WORDS;

    unsigned long long valid =
        ((unsigned long long)g_sval32[c * 64 + 2 * lane + 1] << 32) |
        (unsigned long long)g_sval32[c * 64 + 2 * lane];
    unsigned long long supp = 0ull;
    int cnt = 0;

    for (int ch = 0; ch < wc; ch++) {
        // diagonal words for this chunk (lane l = row (ch*64)+l / +32+l)
        unsigned long long d0 = g_mask[(cbase + ch) * R + (ch << 6) + lane];
        unsigned long long d1 = g_mask[(cbase + ch) * R + (ch << 6) + 32 + lane];
        unsigned long long pend = __shfl_sync(0xFFFFFFFFu, valid & ~supp, ch);
        if (pend == 0ull) continue;

        // in-register greedy over the 64-candidate chunk (ascending order)
        unsigned long long cur = pend, kept = 0ull;
        while (cur) {
            int b = __ffsll((unsigned long long)cur) - 1;
            kept |= 1ull << b;
            unsigned long long w0 = __shfl_sync(0xFFFFFFFFu, d0, b & 31);
            unsigned long long w1 = __shfl_sync(0xFFFFFFFFu, d1, b & 31);
            unsigned long long dw = (b < 32) ? w0 : w1;
            cur &= ~(1ull << b);
            cur &= ~dw;                   // bits <= b already decided; harmless
        }

        // batched cross-chunk suppression (independent loads, one round trip)
        unsigned long long tmp = kept;
        while (tmp) {
            int b = __ffsll((unsigned long long)tmp) - 1;
            tmp &= tmp - 1;
            if (lane < wc)
                supp |= g_mask[(cbase + lane) * R + (ch << 6) + b];
        }

        // record kept indices (ascending), capped at TOPK (beyond-100 within a
        // class can never reach the global top-100)
        if (lane == 0) {
            unsigned long long t2 = kept;
            while (t2 && cnt < TOPK) {
                int b = __ffsll((unsigned long long)t2) - 1;
                t2 &= t2 - 1;
                g_kidx[c * TOPK + cnt] = (unsigned short)((ch << 6) + b);
                cnt++;
            }
        }
        cnt = __shfl_sync(0xFFFFFFFFu, cnt, 0);
    }
    if (lane == 0) g_kcnt[c] = cnt;
}

// ---------------------------------------------------------------------------
// Kernel 4: parallel rank-selection top-100 + outputs.  grid = 1, block = 640.
// ---------------------------------------------------------------------------
__global__ void __launch_bounds__(640, 1)
merge_topk_kernel(const float* __restrict__ boxes, float* __restrict__ out)
{
    __shared__ unsigned long long sKeys[KCLS * TOPK];  // merged keys (score | ~flat)
    __shared__ unsigned long long outk[TOPK];
    __shared__ int scnt[KCLS];
    __shared__ int stot;

    const int t = threadIdx.x;
    if (t < KCLS) scnt[t] = g_kcnt[t];
    __syncthreads();

    // build merged keys: score | ~(global flat index)
    for (int e = t; e < KCLS * TOPK; e += 640) {
        int cc = e / TOPK, p = e % TOPK;
        unsigned long long mk = 0ull;
        if (p < scnt[cc]) {
            int j = g_kidx[e];
            unsigned long long k = g_skey[cc * R + j];
            unsigned int rr = 0xFFFFFFFFu - (unsigned int)(k & 0xFFFFFFFFull);
            unsigned int flat = (unsigned)cc * R + rr;
            mk = (k & 0xFFFFFFFF00000000ull) |
                 (unsigned long long)(0xFFFFFFFFu - flat);
        }
        sKeys[e] = mk;
    }
    if (t == 0) {
        int s = 0;
        for (int cc = 0; cc < KCLS; cc++) s += scnt[cc];
        stot = s;
    }
    __syncthreads();

    // parallel rank selection: rank = own position + binary searches
    for (int e = t; e < KCLS * TOPK; e += 640) {
        int cc = e / TOPK, p = e % TOPK;
        if (p >= scnt[cc]) continue;
        unsigned long long key = sKeys[e];
        int rank = p;
        #pragma unroll
        for (int c2 = 0; c2 < KCLS; c2++) {
            if (c2 == cc) continue;
            int lo = 0, hi = scnt[c2];
            while (lo < hi) {
                int mid = (lo + hi) >> 1;
                if (sKeys[c2 * TOPK + mid] > key) lo = mid + 1; else hi = mid;
            }
            rank += lo;
            if (rank >= TOPK) break;
        }
        if (rank < TOPK) outk[rank] = key;
    }
    __syncthreads();

    // degenerate fallback: fewer than TOPK kept -> -inf entries, lowest
    // non-kept flat index first (matches lax.top_k over the masked matrix)
    if (t == 0 && stot < TOPK) {
        int fill = stot;
        int flat = 0;
        while (fill < TOPK) {
            int cc = flat >> 11;
            int n = scnt[cc];
            bool is_kept = false;
            for (int q = 0; q < n; q++) {
                unsigned int f2 = 0xFFFFFFFFu -
                    (unsigned int)(sKeys[cc * TOPK + q] & 0xFFFFFFFFull);
                if ((int)f2 == flat) { is_kept = true; break; }
            }
            if (!is_kept) {
                outk[fill] = ((unsigned long long)fkey(NEG_INF) << 32) |
                             (unsigned long long)(0xFFFFFFFFu - (unsigned)flat);
                fill++;
            }
            flat++;
        }
    }
    __syncthreads();

    if (t < TOPK) {
        unsigned long long key = outk[t];
        unsigned int flat = 0xFFFFFFFFu - (unsigned int)(key & 0xFFFFFFFFull);
        float sc = fkey_inv((unsigned int)(key >> 32));
        int cls = (int)(flat >> 11);      // R = 2048 = 2^11
        int rr  = (int)(flat & 2047u);
        out[t] = sc;
        out[TOPK + t * 4 + 0] = fminf(fmaxf(boxes[rr * 4 + 0], 0.0f), IMGW);
        out[TOPK + t * 4 + 1] = fminf(fmaxf(boxes[rr * 4 + 1], 0.0f), IMGH);
        out[TOPK + t * 4 + 2] = fminf(fmaxf(boxes[rr * 4 + 2], 0.0f), IMGW);
        out[TOPK + t * 4 + 3] = fminf(fmaxf(boxes[rr * 4 + 3], 0.0f), IMGH);
        out[TOPK + TOPK * 4 + t]        = (float)cls;
        out[TOPK + TOPK * 4 + TOPK + t] = (float)rr;
    }
}

extern "C" void kernel_launch(void* const* d_in, const int* in_sizes, int n_in,
                              void* d_out, int out_size)
{
    const float* boxes  = (const float*)d_in[0];   // [2048,4]
    const float* scores = (const float*)d_in[1];   // [2048,21]
    float* out = (float*)d_out;

    sort_kernel<<<KCLS, 1024>>>(boxes, scores);
    iou_mask_kernel<<<dim3(16, KCLS), 1024>>>();
    nms_reduce_kernel<<<KCLS, 32>>>();
    merge_topk_kernel<<<1, 640>>>(boxes, out);
}